// round 1
// baseline (speedup 1.0000x reference)
#include <cuda_runtime.h>
#include <math.h>

#define N_ROWS 16384
#define D 128
#define INV_T 5.0f      // 1/TEMPERATURE
#define TEMP 0.2f
#define BM 128
#define BN 128
#define CSPLIT 4
#define TILES_PER_SPLIT ((N_ROWS / BN) / CSPLIT)   // 32

// Static device scratch (no allocations allowed)
__device__ float g_feat[N_ROWS * D];   // normalized features, 8 MB
__device__ int   g_lab[N_ROWS];
__device__ float g_S[N_ROWS];          // sum exp(l - 5) over j != i
__device__ float g_P[N_ROWS];          // sum logits over positives j != i
__device__ float g_C[N_ROWS];          // positive count (float)
__device__ int   g_is64;               // label dtype flag

// ---------------------------------------------------------------------------
// Detect whether labels buffer is int64 or int32.
// If int64 (little-endian), every odd int32 word is the high half == 0
// (labels are 0..9). If int32, odd words are labels and are ~never all zero.
__global__ void detect_kernel(const int* __restrict__ lab32) {
    if (threadIdx.x == 0) {
        int any = 0;
        for (int i = 1; i < 64; i += 2) any |= lab32[i];
        g_is64 = (any == 0) ? 1 : 0;
    }
}

// ---------------------------------------------------------------------------
// Normalize rows, convert labels, zero accumulators. One block per row.
__global__ void prep_kernel(const float* __restrict__ feat,
                            const void* __restrict__ labp) {
    int row = blockIdx.x;
    int t = threadIdx.x;           // 128 threads, one per column
    float v = feat[row * D + t];
    float ss = v * v;
    #pragma unroll
    for (int o = 16; o > 0; o >>= 1) ss += __shfl_down_sync(0xffffffffu, ss, o);
    __shared__ float ws[4];
    if ((t & 31) == 0) ws[t >> 5] = ss;
    __syncthreads();
    float tot = ws[0] + ws[1] + ws[2] + ws[3];
    float inv = rsqrtf(tot);
    g_feat[row * D + t] = v * inv;
    if (t == 0) {
        int lab;
        if (g_is64) lab = (int)((const long long*)labp)[row];
        else        lab = ((const int*)labp)[row];
        g_lab[row] = lab;
        g_S[row] = 0.0f;
        g_P[row] = 0.0f;
        g_C[row] = 0.0f;
    }
}

// ---------------------------------------------------------------------------
// Fused Gram + row-stat kernel.
// grid = (N/BM, CSPLIT), block = 256 threads (16x16), 8x8 register tile.
// Shared: As[k][m] (64KB) + Bs[k][n] (64KB) + row labels.
extern __shared__ float sm_main[];

__global__ __launch_bounds__(256, 1) void main_kernel() {
    float* As   = sm_main;                 // [D][BM]
    float* Bs   = sm_main + D * BM;        // [D][BN]
    int*   rlab = (int*)(sm_main + 2 * D * BM);  // [BM]

    const int tid = threadIdx.x;
    const int tx = tid & 15;
    const int ty = tid >> 4;
    const int i0 = blockIdx.x * BM;
    const int split = blockIdx.y;

    // Load A tile transposed: As[k][m] = feat[(i0+m)][k]
    #pragma unroll
    for (int p = 0; p < 16; p++) {
        int k4 = p * 2 + (tid >> 7);   // 0..31
        int m = tid & 127;
        float4 v = *(const float4*)&g_feat[(i0 + m) * D + k4 * 4];
        As[(k4 * 4 + 0) * BM + m] = v.x;
        As[(k4 * 4 + 1) * BM + m] = v.y;
        As[(k4 * 4 + 2) * BM + m] = v.z;
        As[(k4 * 4 + 3) * BM + m] = v.w;
    }
    if (tid < BM) rlab[tid] = g_lab[i0 + tid];

    // per-thread accumulators over all tiles (rows = ty*8..ty*8+7,
    // summed over this thread's 8 columns per tile)
    float accS[8], accP[8];
    int accC[8];
    #pragma unroll
    for (int r = 0; r < 8; r++) { accS[r] = 0.0f; accP[r] = 0.0f; accC[r] = 0; }

    for (int t = 0; t < TILES_PER_SPLIT; t++) {
        const int j0 = (split * TILES_PER_SPLIT + t) * BN;

        __syncthreads();   // As/rlab visible (t=0); prev-tile compute done (t>0)

        // Load B tile transposed: Bs[k][n] = feat[(j0+n)][k]
        #pragma unroll
        for (int p = 0; p < 16; p++) {
            int k4 = p * 2 + (tid >> 7);
            int m = tid & 127;
            float4 v = *(const float4*)&g_feat[(j0 + m) * D + k4 * 4];
            Bs[(k4 * 4 + 0) * BN + m] = v.x;
            Bs[(k4 * 4 + 1) * BN + m] = v.y;
            Bs[(k4 * 4 + 2) * BN + m] = v.z;
            Bs[(k4 * 4 + 3) * BN + m] = v.w;
        }
        __syncthreads();

        float c[8][8];
        #pragma unroll
        for (int r = 0; r < 8; r++)
            #pragma unroll
            for (int q = 0; q < 8; q++) c[r][q] = 0.0f;

        #pragma unroll 8
        for (int k = 0; k < D; k++) {
            float a[8], b[8];
            *(float4*)(a)     = *(const float4*)&As[k * BM + ty * 8];
            *(float4*)(a + 4) = *(const float4*)&As[k * BM + ty * 8 + 4];
            *(float4*)(b)     = *(const float4*)&Bs[k * BN + tx * 8];
            *(float4*)(b + 4) = *(const float4*)&Bs[k * BN + tx * 8 + 4];
            #pragma unroll
            for (int r = 0; r < 8; r++)
                #pragma unroll
                for (int q = 0; q < 8; q++)
                    c[r][q] = fmaf(a[r], b[q], c[r][q]);
        }

        // column labels for this thread's 8 columns
        int lj[8];
        #pragma unroll
        for (int q = 0; q < 8; q++) lj[q] = g_lab[j0 + tx * 8 + q];

        // epilogue: logits = c * (1/T); shift by fixed 5.0 (logits <= 5)
        #pragma unroll
        for (int r = 0; r < 8; r++) {
            const int i = i0 + ty * 8 + r;
            const int li = rlab[ty * 8 + r];
            #pragma unroll
            for (int q = 0; q < 8; q++) {
                const int j = j0 + tx * 8 + q;
                float l = c[r][q] * INV_T;
                if (j != i) {
                    accS[r] += __expf(l - INV_T);
                    if (lj[q] == li) { accP[r] += l; accC[r] += 1; }
                }
            }
        }
    }

    // reduce across the 16 threads (tx) sharing each row, then atomically
    // accumulate into global per-row stats (CSPLIT=4 partial sums per row).
    #pragma unroll
    for (int r = 0; r < 8; r++) {
        float s = accS[r];
        float p = accP[r];
        float cc = (float)accC[r];
        #pragma unroll
        for (int o = 8; o > 0; o >>= 1) {
            s  += __shfl_down_sync(0xffffffffu, s, o, 16);
            p  += __shfl_down_sync(0xffffffffu, p, o, 16);
            cc += __shfl_down_sync(0xffffffffu, cc, o, 16);
        }
        if (tx == 0) {
            int m = i0 + ty * 8 + r;
            atomicAdd(&g_S[m], s);
            atomicAdd(&g_P[m], p);
            atomicAdd(&g_C[m], cc);
        }
    }
}

// ---------------------------------------------------------------------------
// Final scalar reduction. Single block.
__global__ void finish_kernel(float* __restrict__ out) {
    __shared__ float sl[32], sv[32];
    const int tid = threadIdx.x;
    float lsum = 0.0f, vcnt = 0.0f;
    for (int i = tid; i < N_ROWS; i += 1024) {
        float n = g_C[i];
        if (n > 0.5f) {
            // log(denominator) = 5 + log(S)   (fixed shift)
            float pr = g_P[i] / n - INV_T - logf(g_S[i]);
            lsum += -TEMP * pr;
            vcnt += 1.0f;
        }
    }
    #pragma unroll
    for (int o = 16; o > 0; o >>= 1) {
        lsum += __shfl_down_sync(0xffffffffu, lsum, o);
        vcnt += __shfl_down_sync(0xffffffffu, vcnt, o);
    }
    if ((tid & 31) == 0) { sl[tid >> 5] = lsum; sv[tid >> 5] = vcnt; }
    __syncthreads();
    if (tid < 32) {
        float l = sl[tid];
        float v = sv[tid];
        #pragma unroll
        for (int o = 16; o > 0; o >>= 1) {
            l += __shfl_down_sync(0xffffffffu, l, o);
            v += __shfl_down_sync(0xffffffffu, v, o);
        }
        if (tid == 0) out[0] = l / fmaxf(v, 1.0f);
    }
}

// ---------------------------------------------------------------------------
extern "C" void kernel_launch(void* const* d_in, const int* in_sizes, int n_in,
                              void* d_out, int out_size) {
    const float* feat = (const float*)d_in[0];
    const void*  labp = d_in[1];
    float* out = (float*)d_out;

    const int smem_bytes = (2 * D * BM) * (int)sizeof(float) + BM * (int)sizeof(int);
    cudaFuncSetAttribute(main_kernel, cudaFuncAttributeMaxDynamicSharedMemorySize,
                         smem_bytes);

    detect_kernel<<<1, 32>>>((const int*)labp);
    prep_kernel<<<N_ROWS, D>>>(feat, labp);
    dim3 grid(N_ROWS / BM, CSPLIT);
    main_kernel<<<grid, 256, smem_bytes>>>();
    finish_kernel<<<1, 1024>>>(out);
}

// round 4
// speedup vs baseline: 5.8351x; 5.8351x over previous
#include <cuda_runtime.h>
#include <cuda_bf16.h>
#include <stdint.h>
#include <math.h>

#define N_ROWS 16384
#define D 128
#define NCLS 10
#define BM 128
#define BN 128
#define JT 8
#define JGROUPS (N_ROWS / (BN * JT))   // 16

// exp(5c-5) = 2^(c*K1 - K1), K1 = 5*log2(e)
#define K1 7.2134752044448170f

// ---- static device scratch ----
__device__ __align__(16) float          g_feat[N_ROWS * D];    // fp32 normalized
__device__ __align__(16) __nv_bfloat16  g_featb[N_ROWS * D];   // bf16 normalized
__device__ int   g_lab[N_ROWS];
__device__ float g_S[N_ROWS];
__device__ float g_G[D * NCLS];
__device__ int   g_hist[NCLS];
__device__ int   g_is64;
__device__ float g_part[64];
__device__ float g_pcnt[64];

__device__ __forceinline__ uint32_t smem_u32(const void* p) {
    uint32_t a;
    asm("{ .reg .u64 t; cvta.to.shared.u64 t, %1; cvt.u32.u64 %0, t; }" : "=r"(a) : "l"(p));
    return a;
}

// swizzled tile offset: 128 rows x 256B; 16B chunk c at ((c&8)|((c&7)^(row&7)))
__device__ __forceinline__ uint32_t toff(uint32_t row, uint32_t chunk) {
    return row * 256u + (((chunk & 8u) | ((chunk & 7u) ^ (row & 7u))) << 4);
}

#define LDSM4(r, addr)                                                          \
    asm volatile("ldmatrix.sync.aligned.m8n8.x4.shared.b16 {%0,%1,%2,%3}, [%4];"\
        : "=r"((r)[0]), "=r"((r)[1]), "=r"((r)[2]), "=r"((r)[3]) : "r"(addr))

#define MMA16816(c, a, b0, b1)                                                  \
    asm volatile("mma.sync.aligned.m16n8k16.row.col.f32.bf16.bf16.f32 "         \
        "{%0,%1,%2,%3}, {%4,%5,%6,%7}, {%8,%9}, {%0,%1,%2,%3};"                 \
        : "+f"((c)[0]), "+f"((c)[1]), "+f"((c)[2]), "+f"((c)[3])                \
        : "r"((a)[0]), "r"((a)[1]), "r"((a)[2]), "r"((a)[3]), "r"(b0), "r"(b1))

#define CP16(dst, src)                                                          \
    asm volatile("cp.async.cg.shared.global [%0], [%1], 16;" :: "r"(dst), "l"(src))
#define CP_COMMIT() asm volatile("cp.async.commit_group;" ::: "memory")
#define CP_WAIT0()  asm volatile("cp.async.wait_group 0;" ::: "memory")

// ---------------------------------------------------------------------------
__global__ void detect_kernel(const int* __restrict__ lab32) {
    int t = threadIdx.x;                       // 1024
    if (t < D * NCLS) g_G[t] = 0.0f;
    if (t + 1024 < D * NCLS) g_G[t + 1024] = 0.0f;
    if (t < NCLS) g_hist[t] = 0;
    if (t == 0) {
        int any = 0;
        for (int i = 1; i < 64; i += 2) any |= lab32[i];
        g_is64 = (any == 0) ? 1 : 0;
    }
}

// ---------------------------------------------------------------------------
__global__ void prep_kernel(const float* __restrict__ feat,
                            const void* __restrict__ labp) {
    int row = blockIdx.x;
    int t = threadIdx.x;                       // 128
    __shared__ float ws[4];
    __shared__ int slab;
    float v = feat[row * D + t];
    float ss = v * v;
    #pragma unroll
    for (int o = 16; o > 0; o >>= 1) ss += __shfl_down_sync(0xffffffffu, ss, o);
    if (t == 0) {
        int lab;
        if (g_is64) lab = (int)((const long long*)labp)[row];
        else        lab = ((const int*)labp)[row];
        slab = lab;
        g_lab[row] = lab;
        atomicAdd(&g_hist[lab], 1);
        g_S[row] = 0.0f;
    }
    if ((t & 31) == 0) ws[t >> 5] = ss;
    __syncthreads();
    float inv = rsqrtf(ws[0] + ws[1] + ws[2] + ws[3]);
    float nv = v * inv;
    g_feat[row * D + t] = nv;
    g_featb[row * D + t] = __float2bfloat16(nv);
    atomicAdd(&g_G[t * NCLS + slab], nv);
}

// ---------------------------------------------------------------------------
// Fused bf16 Gram + exp-sum. grid=(128,16), block=256 (8 warps: 4M x 2N).
// SMEM: A 32KB | B0 32KB | B1 32KB (double-buffered cp.async).
extern __shared__ char smem[];

__global__ __launch_bounds__(256, 2) void main_kernel() {
    const uint32_t smem_base = smem_u32(smem);
    const uint32_t smA = smem_base;
    const uint32_t smB0 = smem_base + 32768u;
    const int tid = threadIdx.x;
    const int lane = tid & 31;
    const int wid = tid >> 5;
    const int warp_m = wid & 3;
    const int warp_n = wid >> 2;
    const int i0 = blockIdx.x * BM;
    const int jbase = blockIdx.y * (BN * JT);

    // Load A tile (128x128 bf16), swizzled
    {
        #pragma unroll
        for (int it = 0; it < 8; it++) {
            int u = tid + it * 256;
            uint32_t row = (uint32_t)u >> 4, ch = (uint32_t)u & 15;
            *(uint4*)(smem + toff(row, ch)) =
                *(const uint4*)&g_featb[(size_t)(i0 + row) * D + ch * 8];
        }
    }
    // Prefetch B tile 0
    {
        #pragma unroll
        for (int it = 0; it < 8; it++) {
            int u = tid + it * 256;
            uint32_t row = (uint32_t)u >> 4, ch = (uint32_t)u & 15;
            CP16(smB0 + toff(row, ch),
                 (const void*)&g_featb[(size_t)(jbase + row) * D + ch * 8]);
        }
        CP_COMMIT();
    }
    __syncthreads();   // A visible

    // lane-constant addressing
    const int g = lane >> 2;
    const uint32_t swz = (uint32_t)(lane & 7);
    const uint32_t aBase = smA + (uint32_t)(warp_m * 32 + (lane & 15)) * 256u;
    const uint32_t aCh = (uint32_t)(lane >> 4);           // 0/1
    const uint32_t bRowOff = (uint32_t)(warp_n * 64 + (lane & 7) + ((lane >> 4) << 3)) * 256u;
    const uint32_t bCh = (uint32_t)((lane >> 3) & 1);

    float accS[2][2] = {{0.f, 0.f}, {0.f, 0.f}};

    for (int jt = 0; jt < JT; jt++) {
        CP_WAIT0();
        __syncthreads();                       // B[jt&1] ready; prev compute done
        if (jt + 1 < JT) {
            const uint32_t smBn = smB0 + (uint32_t)((jt + 1) & 1) * 32768u;
            const int j0n = jbase + (jt + 1) * BN;
            #pragma unroll
            for (int it = 0; it < 8; it++) {
                int u = tid + it * 256;
                uint32_t row = (uint32_t)u >> 4, ch = (uint32_t)u & 15;
                CP16(smBn + toff(row, ch),
                     (const void*)&g_featb[(size_t)(j0n + row) * D + ch * 8]);
            }
            CP_COMMIT();
        }
        const uint32_t smB = smB0 + (uint32_t)(jt & 1) * 32768u;

        float acc[2][8][4];
        #pragma unroll
        for (int mi = 0; mi < 2; mi++)
            #pragma unroll
            for (int nt = 0; nt < 8; nt++)
                #pragma unroll
                for (int q = 0; q < 4; q++) acc[mi][nt][q] = 0.0f;

        #pragma unroll
        for (int ks = 0; ks < 8; ks++) {
            uint32_t a[2][4];
            const uint32_t ca = (uint32_t)(ks * 2) + aCh;
            const uint32_t aoff = ((ca & 8u) | ((ca & 7u) ^ swz)) << 4;
            LDSM4(a[0], aBase + aoff);
            LDSM4(a[1], aBase + 4096u + aoff);
            const uint32_t cb = (uint32_t)(ks * 2) + bCh;
            const uint32_t boff = ((cb & 8u) | ((cb & 7u) ^ swz)) << 4;
            #pragma unroll
            for (int np = 0; np < 4; np++) {
                uint32_t b[4];
                LDSM4(b, smB + bRowOff + (uint32_t)(np * 16) * 256u + boff);
                MMA16816(acc[0][np * 2],     a[0], b[0], b[1]);
                MMA16816(acc[1][np * 2],     a[1], b[0], b[1]);
                MMA16816(acc[0][np * 2 + 1], a[0], b[2], b[3]);
                MMA16816(acc[1][np * 2 + 1], a[1], b[2], b[3]);
            }
        }

        // epilogue: accS += exp(5c-5) (diagonal included; corrected later)
        #pragma unroll
        for (int mi = 0; mi < 2; mi++) {
            #pragma unroll
            for (int nt = 0; nt < 8; nt++) {
                #pragma unroll
                for (int q = 0; q < 4; q++) {
                    float y = fmaf(acc[mi][nt][q], K1, -K1);
                    float e;
                    asm("ex2.approx.ftz.f32 %0, %1;" : "=f"(e) : "f"(y));
                    accS[mi][q >> 1] += e;     // q<2 -> row g ; q>=2 -> row g+8
                }
            }
        }
    }

    // reduce over the 4 lanes of each quad (they hold disjoint columns)
    #pragma unroll
    for (int mi = 0; mi < 2; mi++)
        #pragma unroll
        for (int r = 0; r < 2; r++) {
            float v = accS[mi][r];
            v += __shfl_xor_sync(0xffffffffu, v, 1);
            v += __shfl_xor_sync(0xffffffffu, v, 2);
            if ((lane & 3) == 0)
                atomicAdd(&g_S[i0 + warp_m * 32 + mi * 16 + g + r * 8], v);
        }
}

// ---------------------------------------------------------------------------
// loss_i = 0.2*(5 + log(S_i - 1) - P_i/C_i), P_i = 5*(F G)[i,lab_i] - 5,
// C_i = hist[lab_i] - 1.
__global__ void partial_kernel() {
    __shared__ float sG[D * NCLS];
    __shared__ float sl[8], sv[8];
    const int tid = threadIdx.x;
    for (int u = tid; u < D * NCLS; u += 256) sG[u] = g_G[u];
    __syncthreads();

    const int i = blockIdx.x * 256 + tid;
    const int lab = g_lab[i];
    const float C = (float)(g_hist[lab] - 1);
    float ls = 0.0f, vv = 0.0f;
    if (C > 0.5f) {
        const float* f = g_feat + (size_t)i * D;
        float d0 = 0.f, d1 = 0.f, d2 = 0.f, d3 = 0.f;
        #pragma unroll
        for (int k = 0; k < D; k += 4) {
            d0 = fmaf(f[k + 0], sG[(k + 0) * NCLS + lab], d0);
            d1 = fmaf(f[k + 1], sG[(k + 1) * NCLS + lab], d1);
            d2 = fmaf(f[k + 2], sG[(k + 2) * NCLS + lab], d2);
            d3 = fmaf(f[k + 3], sG[(k + 3) * NCLS + lab], d3);
        }
        float P = 5.0f * ((d0 + d1) + (d2 + d3)) - 5.0f;
        ls = 0.2f * (5.0f + logf(g_S[i] - 1.0f) - P / C);
        vv = 1.0f;
    }
    #pragma unroll
    for (int o = 16; o > 0; o >>= 1) {
        ls += __shfl_down_sync(0xffffffffu, ls, o);
        vv += __shfl_down_sync(0xffffffffu, vv, o);
    }
    if ((tid & 31) == 0) { sl[tid >> 5] = ls; sv[tid >> 5] = vv; }
    __syncthreads();
    if (tid == 0) {
        float L = 0.f, V = 0.f;
        #pragma unroll
        for (int w = 0; w < 8; w++) { L += sl[w]; V += sv[w]; }
        g_part[blockIdx.x] = L;
        g_pcnt[blockIdx.x] = V;
    }
}

__global__ void final_kernel(float* __restrict__ out) {
    const int t = threadIdx.x;   // 64
    float l = g_part[t], v = g_pcnt[t];
    #pragma unroll
    for (int o = 16; o > 0; o >>= 1) {
        l += __shfl_down_sync(0xffffffffu, l, o);
        v += __shfl_down_sync(0xffffffffu, v, o);
    }
    __shared__ float a[2], b[2];
    if ((t & 31) == 0) { a[t >> 5] = l; b[t >> 5] = v; }
    __syncthreads();
    if (t == 0) out[0] = (a[0] + a[1]) / fmaxf(b[0] + b[1], 1.0f);
}

// ---------------------------------------------------------------------------
extern "C" void kernel_launch(void* const* d_in, const int* in_sizes, int n_in,
                              void* d_out, int out_size) {
    const float* feat = (const float*)d_in[0];
    const void*  labp = d_in[1];
    float* out = (float*)d_out;

    const int smem_bytes = 3 * 32768;
    cudaFuncSetAttribute(main_kernel, cudaFuncAttributeMaxDynamicSharedMemorySize,
                         smem_bytes);

    detect_kernel<<<1, 1024>>>((const int*)labp);
    prep_kernel<<<N_ROWS, D>>>(feat, labp);
    dim3 grid(N_ROWS / BM, JGROUPS);
    main_kernel<<<grid, 256, smem_bytes>>>();
    partial_kernel<<<64, 256>>>();
    final_kernel<<<1, 64>>>(out);
}

// round 5
// speedup vs baseline: 6.9949x; 1.1988x over previous
#include <cuda_runtime.h>
#include <cuda_bf16.h>
#include <stdint.h>
#include <math.h>

#define N_ROWS 16384
#define D 128
#define NCLS 10
#define BM 128
#define BN 128
#define NBLK (N_ROWS / BM)       // 128

// exp(5c-5) = 2^(c*K1 - K1), K1 = 5*log2(e)
#define K1 7.2134752044448170f

// ---- static device scratch ----
__device__ __align__(16) float          g_feat[N_ROWS * D];
__device__ __align__(16) __nv_bfloat16  g_featb[N_ROWS * D];
__device__ int   g_lab[N_ROWS];
__device__ float g_S[N_ROWS];
__device__ float g_G[D * NCLS];
__device__ int   g_hist[NCLS];
__device__ int   g_is64;
__device__ float g_part[2048];
__device__ float g_pcnt[2048];

__device__ __forceinline__ uint32_t smem_u32(const void* p) {
    uint32_t a;
    asm("{ .reg .u64 t; cvta.to.shared.u64 t, %1; cvt.u32.u64 %0, t; }" : "=r"(a) : "l"(p));
    return a;
}

// swizzled tile offset: 128 rows x 256B; 16B chunk c at ((c&8)|((c&7)^(row&7)))
__device__ __forceinline__ uint32_t toff(uint32_t row, uint32_t chunk) {
    return row * 256u + (((chunk & 8u) | ((chunk & 7u) ^ (row & 7u))) << 4);
}

#define LDSM4(r, addr)                                                          \
    asm volatile("ldmatrix.sync.aligned.m8n8.x4.shared.b16 {%0,%1,%2,%3}, [%4];"\
        : "=r"((r)[0]), "=r"((r)[1]), "=r"((r)[2]), "=r"((r)[3]) : "r"(addr))

#define MMA16816(c, a, b0, b1)                                                  \
    asm volatile("mma.sync.aligned.m16n8k16.row.col.f32.bf16.bf16.f32 "         \
        "{%0,%1,%2,%3}, {%4,%5,%6,%7}, {%8,%9}, {%0,%1,%2,%3};"                 \
        : "+f"((c)[0]), "+f"((c)[1]), "+f"((c)[2]), "+f"((c)[3])                \
        : "r"((a)[0]), "r"((a)[1]), "r"((a)[2]), "r"((a)[3]), "r"(b0), "r"(b1))

#define CP16(dst, src)                                                          \
    asm volatile("cp.async.cg.shared.global [%0], [%1], 16;" :: "r"(dst), "l"(src))
#define CP_COMMIT() asm volatile("cp.async.commit_group;" ::: "memory")
#define CP_WAIT0()  asm volatile("cp.async.wait_group 0;" ::: "memory")

// ---------------------------------------------------------------------------
__global__ void detect_kernel(const int* __restrict__ lab32) {
    int t = threadIdx.x;                       // 1024
    if (t < D * NCLS) g_G[t] = 0.0f;
    if (t + 1024 < D * NCLS) g_G[t + 1024] = 0.0f;
    if (t < NCLS) g_hist[t] = 0;
    if (t == 0) {
        int any = 0;
        for (int i = 1; i < 64; i += 2) any |= lab32[i];
        g_is64 = (any == 0) ? 1 : 0;
    }
}

// ---------------------------------------------------------------------------
__global__ void prep_kernel(const float* __restrict__ feat,
                            const void* __restrict__ labp) {
    int row = blockIdx.x;
    int t = threadIdx.x;                       // 128
    __shared__ float ws[4];
    __shared__ int slab;
    float v = feat[row * D + t];
    float ss = v * v;
    #pragma unroll
    for (int o = 16; o > 0; o >>= 1) ss += __shfl_down_sync(0xffffffffu, ss, o);
    if (t == 0) {
        int lab;
        if (g_is64) lab = (int)((const long long*)labp)[row];
        else        lab = ((const int*)labp)[row];
        slab = lab;
        g_lab[row] = lab;
        atomicAdd(&g_hist[lab], 1);
        g_S[row] = 0.0f;
    }
    if ((t & 31) == 0) ws[t >> 5] = ss;
    __syncthreads();
    float inv = rsqrtf(ws[0] + ws[1] + ws[2] + ws[3]);
    float nv = v * inv;
    g_feat[row * D + t] = nv;
    g_featb[row * D + t] = __float2bfloat16(nv);
    atomicAdd(&g_G[t * NCLS + slab], nv);
}

// ---------------------------------------------------------------------------
// Symmetric fused Gram + exp-sum. grid=(128, 8): bi = x, d-chunk = y.
// Tile t: d = chunk*8 + t, bj = (bi+d) & 127. Chunk 7 adds d=64 for bi<64.
// Each tile adds exp-sums to rows of block bi AND (d>0) rows of block bj.
extern __shared__ char smem[];

__global__ __launch_bounds__(256, 2) void main_kernel() {
    const uint32_t smem_base = smem_u32(smem);
    const uint32_t smA = smem_base;
    const uint32_t smB0 = smem_base + 32768u;
    const int tid = threadIdx.x;
    const int lane = tid & 31;
    const int wid = tid >> 5;
    const int warp_m = wid & 3;
    const int warp_n = wid >> 2;
    const int bi = blockIdx.x;
    const int chunk = blockIdx.y;
    const int i0 = bi * BM;
    const int d0 = chunk * 8;
    const int ntiles = (chunk == 7 && bi < 64) ? 9 : 8;

    // Load A tile (block bi), swizzled (direct stores; small, once per CTA)
    #pragma unroll
    for (int it = 0; it < 8; it++) {
        int u = tid + it * 256;
        uint32_t row = (uint32_t)u >> 4, ch = (uint32_t)u & 15;
        *(uint4*)(smem + toff(row, ch)) =
            *(const uint4*)&g_featb[(size_t)(i0 + row) * D + ch * 8];
    }
    // Prefetch B tile 0 (bj = (bi + d0) & 127)
    {
        const int j0 = ((bi + d0) & (NBLK - 1)) * BN;
        #pragma unroll
        for (int it = 0; it < 8; it++) {
            int u = tid + it * 256;
            uint32_t row = (uint32_t)u >> 4, ch = (uint32_t)u & 15;
            CP16(smB0 + toff(row, ch),
                 (const void*)&g_featb[(size_t)(j0 + row) * D + ch * 8]);
        }
        CP_COMMIT();
    }
    __syncthreads();   // A visible

    const int g = lane >> 2;
    const uint32_t swz = (uint32_t)(lane & 7);
    const uint32_t aBase = smA + (uint32_t)(warp_m * 32 + (lane & 15)) * 256u;
    const uint32_t aCh = (uint32_t)(lane >> 4);
    const uint32_t bRowOff = (uint32_t)(warp_n * 64 + (lane & 7) + ((lane >> 4) << 3)) * 256u;
    const uint32_t bCh = (uint32_t)((lane >> 3) & 1);

    float accS[2][2] = {{0.f, 0.f}, {0.f, 0.f}};

    for (int jt = 0; jt < ntiles; jt++) {
        const int d = d0 + jt;
        const int j0 = ((bi + d) & (NBLK - 1)) * BN;

        CP_WAIT0();
        __syncthreads();                       // B[jt&1] ready; prev compute done
        if (jt + 1 < ntiles) {
            const uint32_t smBn = smB0 + (uint32_t)((jt + 1) & 1) * 32768u;
            const int j0n = ((bi + d + 1) & (NBLK - 1)) * BN;
            #pragma unroll
            for (int it = 0; it < 8; it++) {
                int u = tid + it * 256;
                uint32_t row = (uint32_t)u >> 4, ch = (uint32_t)u & 15;
                CP16(smBn + toff(row, ch),
                     (const void*)&g_featb[(size_t)(j0n + row) * D + ch * 8]);
            }
            CP_COMMIT();
        }
        const uint32_t smB = smB0 + (uint32_t)(jt & 1) * 32768u;

        float acc[2][8][4];
        #pragma unroll
        for (int mi = 0; mi < 2; mi++)
            #pragma unroll
            for (int nt = 0; nt < 8; nt++)
                #pragma unroll
                for (int q = 0; q < 4; q++) acc[mi][nt][q] = 0.0f;

        #pragma unroll
        for (int ks = 0; ks < 8; ks++) {
            uint32_t a[2][4];
            const uint32_t ca = (uint32_t)(ks * 2) + aCh;
            const uint32_t aoff = ((ca & 8u) | ((ca & 7u) ^ swz)) << 4;
            LDSM4(a[0], aBase + aoff);
            LDSM4(a[1], aBase + 4096u + aoff);
            const uint32_t cb = (uint32_t)(ks * 2) + bCh;
            const uint32_t boff = ((cb & 8u) | ((cb & 7u) ^ swz)) << 4;
            #pragma unroll
            for (int np = 0; np < 4; np++) {
                uint32_t b[4];
                LDSM4(b, smB + bRowOff + (uint32_t)(np * 16) * 256u + boff);
                MMA16816(acc[0][np * 2],     a[0], b[0], b[1]);
                MMA16816(acc[1][np * 2],     a[1], b[0], b[1]);
                MMA16816(acc[0][np * 2 + 1], a[0], b[2], b[3]);
                MMA16816(acc[1][np * 2 + 1], a[1], b[2], b[3]);
            }
        }

        // epilogue: e = exp(5c-5); rows of bi always; cols -> rows of bj (d>0)
        float accC[8][2];
        #pragma unroll
        for (int nt = 0; nt < 8; nt++) { accC[nt][0] = 0.f; accC[nt][1] = 0.f; }

        #pragma unroll
        for (int mi = 0; mi < 2; mi++) {
            #pragma unroll
            for (int nt = 0; nt < 8; nt++) {
                #pragma unroll
                for (int q = 0; q < 4; q++) {
                    float y = fmaf(acc[mi][nt][q], K1, -K1);
                    float e;
                    asm("ex2.approx.ftz.f32 %0, %1;" : "=f"(e) : "f"(y));
                    accS[mi][q >> 1] += e;
                    accC[nt][q & 1] += e;
                }
            }
        }

        if (d != 0) {
            // col sums: reduce over g (lanes xor 4,8,16); lanes 0..3 hold cols
            #pragma unroll
            for (int nt = 0; nt < 8; nt++) {
                #pragma unroll
                for (int p = 0; p < 2; p++) {
                    float v = accC[nt][p];
                    v += __shfl_xor_sync(0xffffffffu, v, 4);
                    v += __shfl_xor_sync(0xffffffffu, v, 8);
                    v += __shfl_xor_sync(0xffffffffu, v, 16);
                    if (lane < 4)
                        atomicAdd(&g_S[j0 + warp_n * 64 + nt * 8 + 2 * lane + p], v);
                }
            }
        }
    }

    // row sums: reduce over quad lanes (disjoint columns), one atomic per row
    #pragma unroll
    for (int mi = 0; mi < 2; mi++)
        #pragma unroll
        for (int r = 0; r < 2; r++) {
            float v = accS[mi][r];
            v += __shfl_xor_sync(0xffffffffu, v, 1);
            v += __shfl_xor_sync(0xffffffffu, v, 2);
            if ((lane & 3) == 0)
                atomicAdd(&g_S[i0 + warp_m * 32 + mi * 16 + g + r * 8], v);
        }
}

// ---------------------------------------------------------------------------
// Warp-per-row: loss_i = 0.2*(5 + log(S_i - 1) - P_i/C_i),
// P_i = 5*(F G)[i,lab_i] - 5, C_i = hist[lab_i]-1. grid 2048, block 256.
__global__ void partial_kernel() {
    __shared__ float sG[D * NCLS];
    __shared__ float sl[8], sv[8];
    const int tid = threadIdx.x;
    const int lane = tid & 31;
    const int wid = tid >> 5;
    for (int u = tid; u < D * NCLS; u += 256) sG[u] = g_G[u];
    __syncthreads();

    const int row = blockIdx.x * 8 + wid;
    const int lab = g_lab[row];
    const float C = (float)(g_hist[lab] - 1);
    float4 f4 = *(const float4*)&g_feat[(size_t)row * D + lane * 4];
    float dd = f4.x * sG[(lane * 4 + 0) * NCLS + lab]
             + f4.y * sG[(lane * 4 + 1) * NCLS + lab]
             + f4.z * sG[(lane * 4 + 2) * NCLS + lab]
             + f4.w * sG[(lane * 4 + 3) * NCLS + lab];
    #pragma unroll
    for (int o = 16; o > 0; o >>= 1) dd += __shfl_down_sync(0xffffffffu, dd, o);

    if (lane == 0) {
        float ls = 0.0f, vv = 0.0f;
        if (C > 0.5f) {
            float P = 5.0f * dd - 5.0f;
            ls = 0.2f * (5.0f + logf(g_S[row] - 1.0f) - P / C);
            vv = 1.0f;
        }
        sl[wid] = ls; sv[wid] = vv;
    }
    __syncthreads();
    if (tid == 0) {
        float L = 0.f, V = 0.f;
        #pragma unroll
        for (int w = 0; w < 8; w++) { L += sl[w]; V += sv[w]; }
        g_part[blockIdx.x] = L;
        g_pcnt[blockIdx.x] = V;
    }
}

__global__ void final_kernel(float* __restrict__ out) {
    const int t = threadIdx.x;   // 1024
    float l = g_part[t] + g_part[t + 1024];
    float v = g_pcnt[t] + g_pcnt[t + 1024];
    #pragma unroll
    for (int o = 16; o > 0; o >>= 1) {
        l += __shfl_down_sync(0xffffffffu, l, o);
        v += __shfl_down_sync(0xffffffffu, v, o);
    }
    __shared__ float a[32], b[32];
    if ((t & 31) == 0) { a[t >> 5] = l; b[t >> 5] = v; }
    __syncthreads();
    if (t < 32) {
        float L = a[t], V = b[t];
        #pragma unroll
        for (int o = 16; o > 0; o >>= 1) {
            L += __shfl_down_sync(0xffffffffu, L, o);
            V += __shfl_down_sync(0xffffffffu, V, o);
        }
        if (t == 0) out[0] = L / fmaxf(V, 1.0f);
    }
}

// ---------------------------------------------------------------------------
extern "C" void kernel_launch(void* const* d_in, const int* in_sizes, int n_in,
                              void* d_out, int out_size) {
    const float* feat = (const float*)d_in[0];
    const void*  labp = d_in[1];
    float* out = (float*)d_out;

    const int smem_bytes = 3 * 32768;
    cudaFuncSetAttribute(main_kernel, cudaFuncAttributeMaxDynamicSharedMemorySize,
                         smem_bytes);

    detect_kernel<<<1, 1024>>>((const int*)labp);
    prep_kernel<<<N_ROWS, D>>>(feat, labp);
    dim3 grid(NBLK, 8);
    main_kernel<<<grid, 256, smem_bytes>>>();
    partial_kernel<<<2048, 256>>>();
    final_kernel<<<1, 1024>>>(out);
}